// round 2
// baseline (speedup 1.0000x reference)
#include <cuda_runtime.h>
#include <math.h>

#define T_LEN  (1 << 20)
#define CPT    16                  // elements per thread
#define BLK    256
#define CHUNK  (BLK * CPT)         // 4096
#define NCHUNK (T_LEN / CHUNK)     // 256
#define NB     4
#define EPSF   1e-8f
#define P3BLKS 128

struct Consts {
    float c[6];   // EMA coefficient (float32, matching reference cast)
    float a[6];   // 1 - c (float32)
    float aC[6];  // a^CPT   (double-pow, rounded)
    float aL[6];  // a^CHUNK
};

// Scratch (static device allocations — no cudaMalloc allowed)
__device__ float g_r [NB][24][NCHUNK];     // chunk-local decayed sums
__device__ float g_cc[NB][24][NCHUNK];     // carry into each chunk
__device__ float g_AB[8][6][T_LEN];        // [row][feat] feat 0..2 = A_i, 3..5 = B_i (swizzled t layout)
__device__ float g_part[24 * P3BLKS];

// Chain layout: c = rm*12 + sig*6 + k  (rm: 0=mid 1=side, sig: 0=pred 1=true, k: 0..2 short / 3..5 long)
__device__ __forceinline__ void chain_update(float* y, const Consts& K,
                                             float vpm, float vtm, float vps, float vts) {
#pragma unroll
    for (int k = 0; k < 6; k++) {
        y[k]      = fmaf(K.a[k], y[k],      K.c[k] * vpm);
        y[6 + k]  = fmaf(K.a[k], y[6 + k],  K.c[k] * vtm);
        y[12 + k] = fmaf(K.a[k], y[12 + k], K.c[k] * vps);
        y[18 + k] = fmaf(K.a[k], y[18 + k], K.c[k] * vts);
    }
}

#define DO_ELEM(e) {                                                         \
    float sm = a0.e + a1.e, sd = a0.e - a1.e;                                \
    float tm = b0.e + b1.e, td = b0.e - b1.e;                                \
    chain_update(y, K, fmaxf(0.5f * sm * sm, EPSF),                          \
                       fmaxf(0.5f * tm * tm, EPSF),                          \
                       fmaxf(0.5f * sd * sd, EPSF),                          \
                       fmaxf(0.5f * td * td, EPSF)); }

__device__ __forceinline__ void local_accum(float* y, const Consts& K,
        const float4* __restrict__ p0, const float4* __restrict__ p1,
        const float4* __restrict__ q0, const float4* __restrict__ q1) {
#pragma unroll
    for (int jj = 0; jj < CPT / 4; jj++) {
        float4 a0 = p0[jj], a1 = p1[jj], b0 = q0[jj], b1 = q1[jj];
        DO_ELEM(x) DO_ELEM(y) DO_ELEM(z) DO_ELEM(w)
    }
}

// Decayed inclusive Hillis-Steele scan over threads; multiplier doubles by squaring.
__device__ __forceinline__ void block_scan(float (*ss)[BLK], const float* y,
                                           const Consts& K, int tid) {
#pragma unroll
    for (int c = 0; c < 24; c++) ss[c][tid] = y[c];
    __syncthreads();
    float pw[6];
#pragma unroll
    for (int k = 0; k < 6; k++) pw[k] = K.aC[k];
    for (int off = 1; off < BLK; off <<= 1) {
        float tmp[24];
#pragma unroll
        for (int c = 0; c < 24; c++) tmp[c] = (tid >= off) ? ss[c][tid - off] : 0.0f;
        __syncthreads();
#pragma unroll
        for (int c = 0; c < 24; c++) ss[c][tid] = fmaf(pw[c % 6], tmp[c], ss[c][tid]);
#pragma unroll
        for (int k = 0; k < 6; k++) pw[k] *= pw[k];
        __syncthreads();
    }
}

__global__ __launch_bounds__(BLK) void pass1_kernel(const float* __restrict__ xp,
                                                    const float* __restrict__ xt, Consts K) {
    __shared__ float ss[24][BLK];
    int g = blockIdx.x, b = blockIdx.y, tid = threadIdx.x;
    size_t base = (size_t)g * CHUNK + (size_t)tid * CPT;
    const float4* p0 = (const float4*)(xp + (size_t)(b * 2 + 0) * T_LEN + base);
    const float4* p1 = (const float4*)(xp + (size_t)(b * 2 + 1) * T_LEN + base);
    const float4* q0 = (const float4*)(xt + (size_t)(b * 2 + 0) * T_LEN + base);
    const float4* q1 = (const float4*)(xt + (size_t)(b * 2 + 1) * T_LEN + base);
    float y[24];
#pragma unroll
    for (int c = 0; c < 24; c++) y[c] = 0.0f;
    local_accum(y, K, p0, p1, q0, q1);
    block_scan(ss, y, K, tid);
    if (tid == BLK - 1) {
#pragma unroll
        for (int c = 0; c < 24; c++) g_r[b][c][g] = ss[c][BLK - 1];
    }
}

__global__ void mid_kernel(Consts K) {
    int id = threadIdx.x;
    if (id >= NB * 24) return;
    int b = id / 24, c = id % 24, k = c % 6;
    float aL = K.aL[k];
    float cc = 0.0f;
    for (int g = 0; g < NCHUNK; g++) {
        g_cc[b][c][g] = cc;
        cc = fmaf(aL, cc, g_r[b][c][g]);
    }
}

__global__ __launch_bounds__(BLK) void pass2_kernel(const float* __restrict__ xp,
                                                    const float* __restrict__ xt, Consts K) {
    __shared__ float ss[24][BLK];
    int g = blockIdx.x, b = blockIdx.y, tid = threadIdx.x;
    size_t base = (size_t)g * CHUNK + (size_t)tid * CPT;
    const float4* p0 = (const float4*)(xp + (size_t)(b * 2 + 0) * T_LEN + base);
    const float4* p1 = (const float4*)(xp + (size_t)(b * 2 + 1) * T_LEN + base);
    const float4* q0 = (const float4*)(xt + (size_t)(b * 2 + 0) * T_LEN + base);
    const float4* q1 = (const float4*)(xt + (size_t)(b * 2 + 1) * T_LEN + base);

    float y[24];
#pragma unroll
    for (int c = 0; c < 24; c++) y[c] = 0.0f;
    local_accum(y, K, p0, p1, q0, q1);

    if (tid == 0) {  // seed thread0 with chunk carry so scan propagates it exactly
#pragma unroll
        for (int c = 0; c < 24; c++) y[c] = fmaf(K.aC[c % 6], g_cc[b][c][g], y[c]);
    }
    block_scan(ss, y, K, tid);

    float cin[24];
    if (tid == 0) {
#pragma unroll
        for (int c = 0; c < 24; c++) cin[c] = g_cc[b][c][g];
    } else {
#pragma unroll
        for (int c = 0; c < 24; c++) cin[c] = ss[c][tid - 1];
    }

    int row0 = b * 2, row1 = b * 2 + 1;
    int obase = g * CHUNK;
#pragma unroll
    for (int jj = 0; jj < CPT / 4; jj++) {
        float4 a0 = p0[jj], a1 = p1[jj], b0 = q0[jj], b1 = q1[jj];
#define OUT_ELEM(e, eidx) {                                                  \
        float sm = a0.e + a1.e, sd = a0.e - a1.e;                            \
        float tm = b0.e + b1.e, td = b0.e - b1.e;                            \
        chain_update(cin, K, fmaxf(0.5f * sm * sm, EPSF),                    \
                             fmaxf(0.5f * tm * tm, EPSF),                    \
                             fmaxf(0.5f * sd * sd, EPSF),                    \
                             fmaxf(0.5f * td * td, EPSF));                   \
        int addr = obase + (jj * 4 + eidx) * BLK + tid;                      \
        _Pragma("unroll")                                                    \
        for (int i = 0; i < 3; i++) {                                        \
            g_AB[row0][i][addr]     = __log2f(cin[i])      - __log2f(cin[6 + i]);   \
            g_AB[row0][3 + i][addr] = __log2f(cin[3 + i])  - __log2f(cin[9 + i]);   \
            g_AB[row1][i][addr]     = __log2f(cin[12 + i]) - __log2f(cin[18 + i]);  \
            g_AB[row1][3 + i][addr] = __log2f(cin[15 + i]) - __log2f(cin[21 + i]);  \
        } }
        OUT_ELEM(x, 0) OUT_ELEM(y, 1) OUT_ELEM(z, 2) OUT_ELEM(w, 3)
#undef OUT_ELEM
    }
}

// Swizzled layout: time t = g*4096 + th*16 + j is stored at addr = g*4096 + j*256 + th.
// Linear addr iteration => t strides by 16 => shifted B address strides by 1: both coalesced.
__global__ __launch_bounds__(256) void pass3_kernel() {
    int tid = threadIdx.x;
    int combo = blockIdx.y;              // 24 = 8 rows x 3 pairs
    int row = combo / 3, i = combo % 3;
    int shift = (i == 0) ? 10804 : (i == 1) ? 31972 : 63945;
    const float* __restrict__ A = g_AB[row][i];
    const float* __restrict__ B = g_AB[row][3 + i];
    float acc = 0.0f;
    for (int lin = blockIdx.x * 256 + tid; lin < T_LEN; lin += gridDim.x * 256) {
        int rem  = lin & (CHUNK - 1);
        int t    = (lin & ~(CHUNK - 1)) + (rem & (BLK - 1)) * CPT + (rem >> 8);
        int t2   = (t + shift) & (T_LEN - 1);
        int rem2 = t2 & (CHUNK - 1);
        int addr2 = (t2 & ~(CHUNK - 1)) + ((rem2 & (CPT - 1)) << 8) + (rem2 >> 4);
        acc += fabsf(A[lin] - B[addr2]);
    }
    __shared__ float sh[256];
    sh[tid] = acc;
    __syncthreads();
    for (int s = 128; s > 0; s >>= 1) {
        if (tid < s) sh[tid] += sh[tid + s];
        __syncthreads();
    }
    if (tid == 0) g_part[combo * gridDim.x + blockIdx.x] = sh[0];
}

__global__ void final_kernel(float* __restrict__ out) {
    __shared__ float sh[1024];
    int tid = threadIdx.x;
    float v = 0.0f;
    for (int i = tid; i < 24 * P3BLKS; i += 1024) v += g_part[i];
    sh[tid] = v;
    __syncthreads();
    for (int s = 512; s > 0; s >>= 1) {
        if (tid < s) sh[tid] += sh[tid + s];
        __syncthreads();
    }
    if (tid == 0)
        out[0] = (float)((double)sh[0] * 0.69314718055994530942 / (8.0 * (double)T_LEN));
}

extern "C" void kernel_launch(void* const* d_in, const int* in_sizes, int n_in,
                              void* d_out, int out_size) {
    const float* xp = (const float*)d_in[0];
    const float* xt = (const float*)d_in[1];
    (void)in_sizes; (void)n_in; (void)out_size;

    Consts K;
    const double sr = 44100.0;
    const double s_taus[3] = {10.0, 50.0, 100.0};
    const double l_taus[3] = {500.0, 1500.0, 3000.0};
    for (int i = 0; i < 3; i++) {
        K.c[i]     = (float)(1.0 - exp(-2200.0 / (s_taus[i] * sr)));
        K.c[3 + i] = (float)(1.0 - exp(-2200.0 / (l_taus[i] * sr)));
    }
    for (int k = 0; k < 6; k++) {
        K.a[k]  = 1.0f - K.c[k];
        K.aC[k] = (float)pow((double)K.a[k], (double)CPT);
        K.aL[k] = (float)pow((double)K.a[k], (double)CHUNK);
    }

    dim3 grid(NCHUNK, NB);
    pass1_kernel<<<grid, BLK>>>(xp, xt, K);
    mid_kernel<<<1, 128>>>(K);
    pass2_kernel<<<grid, BLK>>>(xp, xt, K);
    dim3 g3(P3BLKS, 24);
    pass3_kernel<<<g3, 256>>>();
    final_kernel<<<1, 1024>>>((float*)d_out);
}

// round 3
// speedup vs baseline: 1.7469x; 1.7469x over previous
#include <cuda_runtime.h>
#include <cuda_fp16.h>
#include <math.h>

#define T_LEN  (1 << 20)
#define CPT    16                  // elements per thread
#define BLK    256
#define CHUNK  (BLK * CPT)         // 4096
#define NCHUNK (T_LEN / CHUNK)     // 256
#define NB     4
#define EPSF   1e-8f
#define P3BLKS 32

struct Consts {
    float c[6];   // EMA coefficient
    float a[6];   // 1 - c
    float aC[6];  // a^CPT
    float aL[6];  // a^CHUNK
};

// Static device scratch (no cudaMalloc allowed)
__device__ float g_r [NB][24][NCHUNK];            // chunk-local decayed sums
__device__ float g_cc[NB][24][NCHUNK];            // carry into each chunk
__device__ __align__(16) __half g_A[8][3][T_LEN]; // short log-diff, swizzled addr(t)
__device__ __align__(16) __half g_C[8][3][T_LEN]; // long  log-diff, stored pre-shifted
__device__ float g_part[24 * P3BLKS];

// Chain layout: ch = rm*12 + sig*6 + k (rm 0=mid 1=side; sig 0=pred 1=true; k 0..2 short, 3..5 long)
__device__ __forceinline__ void chain_update(float* y, const Consts& K,
                                             float vpm, float vtm, float vps, float vts) {
#pragma unroll
    for (int k = 0; k < 6; k++) {
        y[k]      = fmaf(K.a[k], y[k],      K.c[k] * vpm);
        y[6 + k]  = fmaf(K.a[k], y[6 + k],  K.c[k] * vtm);
        y[12 + k] = fmaf(K.a[k], y[12 + k], K.c[k] * vps);
        y[18 + k] = fmaf(K.a[k], y[18 + k], K.c[k] * vts);
    }
}

#define DO_ELEM(e) {                                                         \
    float sm = a0.e + a1.e, sd = a0.e - a1.e;                                \
    float tm = b0.e + b1.e, td = b0.e - b1.e;                                \
    chain_update(y, K, fmaxf(0.5f * sm * sm, EPSF),                          \
                       fmaxf(0.5f * tm * tm, EPSF),                          \
                       fmaxf(0.5f * sd * sd, EPSF),                          \
                       fmaxf(0.5f * td * td, EPSF)); }

__device__ __forceinline__ void local_accum(float* y, const Consts& K,
        const float4* __restrict__ p0, const float4* __restrict__ p1,
        const float4* __restrict__ q0, const float4* __restrict__ q1) {
#pragma unroll
    for (int jj = 0; jj < CPT / 4; jj++) {
        float4 a0 = p0[jj], a1 = p1[jj], b0 = q0[jj], b1 = q1[jj];
        DO_ELEM(x) DO_ELEM(y) DO_ELEM(z) DO_ELEM(w)
    }
}

// Warp-level decayed inclusive scan of 24 channels + cross-warp combine via 768B smem.
// In: v = per-thread segment totals. Out (FULL=true): v = block-inclusive I, P = warp prefix I_{32w-1}.
// total_out (if non-null): tid<24 writes block total to total_out[tid*NCHUNK].
template <bool FULL>
__device__ __forceinline__ void block_decay_scan(float* v, const Consts& K, int tid,
                                                 float (*wagg)[8], float* P,
                                                 float* total_out) {
    int lane = tid & 31, warp = tid >> 5;
    float pw[6];
#pragma unroll
    for (int k = 0; k < 6; k++) pw[k] = K.aC[k];
#pragma unroll
    for (int off = 1; off < 32; off <<= 1) {
#pragma unroll
        for (int c = 0; c < 24; c++) {
            float up = __shfl_up_sync(0xffffffffu, v[c], off);
            if (lane >= off) v[c] = fmaf(pw[c % 6], up, v[c]);
        }
#pragma unroll
        for (int k = 0; k < 6; k++) pw[k] *= pw[k];   // ends at aC^32
    }
    if (lane == 31) {
#pragma unroll
        for (int c = 0; c < 24; c++) wagg[c][warp] = v[c];
    }
    __syncthreads();
    if (tid < 24) {
        float p = 0.0f, aW = pw[tid % 6];
#pragma unroll
        for (int w = 0; w < 8; w++) {
            float tv = wagg[tid][w];
            wagg[tid][w] = p;               // exclusive warp prefix
            p = fmaf(aW, p, tv);
        }
        if (total_out) total_out[tid * NCHUNK] = p;   // block total
    }
    __syncthreads();
    if (FULL) {
#pragma unroll
        for (int c = 0; c < 24; c++) P[c] = wagg[c][warp];
        // aC^(lane+1) via exact squaring ladder
        float al[6];
#pragma unroll
        for (int k = 0; k < 6; k++) {
            float p = 1.0f, b = K.aC[k];
            int e = lane + 1;
#pragma unroll
            for (int bit = 0; bit < 6; bit++) { if (e & (1 << bit)) p *= b; b *= b; }
            al[k] = p;
        }
#pragma unroll
        for (int c = 0; c < 24; c++) v[c] = fmaf(al[c % 6], P[c], v[c]);
    }
}

__global__ __launch_bounds__(BLK) void pass1_kernel(const float* __restrict__ xp,
                                                    const float* __restrict__ xt, Consts K) {
    __shared__ float wagg[24][8];
    int g = blockIdx.x, b = blockIdx.y, tid = threadIdx.x;
    size_t base = (size_t)g * CHUNK + (size_t)tid * CPT;
    const float4* p0 = (const float4*)(xp + (size_t)(b * 2 + 0) * T_LEN + base);
    const float4* p1 = (const float4*)(xp + (size_t)(b * 2 + 1) * T_LEN + base);
    const float4* q0 = (const float4*)(xt + (size_t)(b * 2 + 0) * T_LEN + base);
    const float4* q1 = (const float4*)(xt + (size_t)(b * 2 + 1) * T_LEN + base);
    float y[24];
#pragma unroll
    for (int c = 0; c < 24; c++) y[c] = 0.0f;
    local_accum(y, K, p0, p1, q0, q1);
    block_decay_scan<false>(y, K, tid, wagg, nullptr, &g_r[b][0][g]);
}

// 96 warp-scans: one block per (batch, chain); each propagates 256 chunk carries.
__global__ void mid_kernel(Consts K) {
    int blk = blockIdx.x;                 // 0..95
    int b = blk / 24, c = blk % 24, k = c % 6;
    int lane = threadIdx.x;
    float aL = K.aL[k];
    float aL8 = aL * aL; aL8 *= aL8; aL8 *= aL8;   // aL^8

    const float* src = &g_r[b][c][lane * 8];
    float r[8], I[8];
    float p = 0.0f;
#pragma unroll
    for (int u = 0; u < 8; u++) { r[u] = src[u]; p = fmaf(aL, p, r[u]); I[u] = p; }

    float tot = I[7], pw = aL8;
#pragma unroll
    for (int off = 1; off < 32; off <<= 1) {
        float up = __shfl_up_sync(0xffffffffu, tot, off);
        if (lane >= off) tot = fmaf(pw, up, tot);
        pw *= pw;
    }
    float P = __shfl_up_sync(0xffffffffu, tot, 1);
    if (lane == 0) P = 0.0f;

    float* dst = &g_cc[b][c][lane * 8];
    dst[0] = P;
    float alu = 1.0f;
#pragma unroll
    for (int u = 1; u < 8; u++) { alu *= aL; dst[u] = fmaf(alu, P, I[u - 1]); }
}

__global__ __launch_bounds__(BLK) void pass2_kernel(const float* __restrict__ xp,
                                                    const float* __restrict__ xt, Consts K,
                                                    int sh0, int sh1, int sh2) {
    __shared__ float wagg[24][8];
    int g = blockIdx.x, b = blockIdx.y, tid = threadIdx.x;
    int lane = tid & 31;
    size_t base = (size_t)g * CHUNK + (size_t)tid * CPT;
    const float4* p0 = (const float4*)(xp + (size_t)(b * 2 + 0) * T_LEN + base);
    const float4* p1 = (const float4*)(xp + (size_t)(b * 2 + 1) * T_LEN + base);
    const float4* q0 = (const float4*)(xt + (size_t)(b * 2 + 0) * T_LEN + base);
    const float4* q1 = (const float4*)(xt + (size_t)(b * 2 + 1) * T_LEN + base);

    float cc[24];
#pragma unroll
    for (int c = 0; c < 24; c++) cc[c] = g_cc[b][c][g];

    float y[24];
#pragma unroll
    for (int c = 0; c < 24; c++) y[c] = 0.0f;
    local_accum(y, K, p0, p1, q0, q1);

    if (tid == 0) {   // seed so the scan propagates the chunk carry exactly
#pragma unroll
        for (int c = 0; c < 24; c++) y[c] = fmaf(K.aC[c % 6], cc[c], y[c]);
    }

    float P[24];
    block_decay_scan<true>(y, K, tid, wagg, P, nullptr);

    float cin[24];
#pragma unroll
    for (int c = 0; c < 24; c++) {
        float prev = __shfl_up_sync(0xffffffffu, y[c], 1);
        cin[c] = (lane == 0) ? P[c] : prev;
    }
    if (tid == 0) {
#pragma unroll
        for (int c = 0; c < 24; c++) cin[c] = cc[c];
    }

    int row0 = b * 2, row1 = b * 2 + 1;
    int obase = g * CHUNK;
    int shifts[3] = {sh0, sh1, sh2};

#pragma unroll
    for (int jj = 0; jj < CPT / 4; jj++) {
        float4 a0 = p0[jj], a1 = p1[jj], b0 = q0[jj], b1 = q1[jj];
#define OUT_ELEM(e, eidx) {                                                      \
        float sm = a0.e + a1.e, sd = a0.e - a1.e;                                \
        float tm = b0.e + b1.e, td = b0.e - b1.e;                                \
        chain_update(cin, K, fmaxf(0.5f * sm * sm, EPSF),                        \
                             fmaxf(0.5f * tm * tm, EPSF),                        \
                             fmaxf(0.5f * sd * sd, EPSF),                        \
                             fmaxf(0.5f * td * td, EPSF));                       \
        int el = jj * 4 + eidx;                                                  \
        int addr = obase + el * BLK + tid;                                       \
        int t = obase + tid * CPT + el;                                          \
        _Pragma("unroll")                                                        \
        for (int i = 0; i < 3; i++) {                                            \
            g_A[row0][i][addr] = __float2half(__log2f(cin[i])      - __log2f(cin[6 + i]));  \
            g_A[row1][i][addr] = __float2half(__log2f(cin[12 + i]) - __log2f(cin[18 + i])); \
            int t2 = (t - shifts[i]) & (T_LEN - 1);                              \
            int caddr = (t2 & ~(CHUNK - 1)) | ((t2 & (CPT - 1)) << 8)            \
                      | ((t2 & (CHUNK - 1)) >> 4);                               \
            g_C[row0][i][caddr] = __float2half(__log2f(cin[3 + i])  - __log2f(cin[9 + i]));  \
            g_C[row1][i][caddr] = __float2half(__log2f(cin[15 + i]) - __log2f(cin[21 + i])); \
        } }
        OUT_ELEM(x, 0) OUT_ELEM(y, 1) OUT_ELEM(z, 2) OUT_ELEM(w, 3)
#undef OUT_ELEM
    }
}

// Both streams linear + 16B aligned (B pre-shifted at write time).
__global__ __launch_bounds__(256) void pass3_kernel() {
    int tid = threadIdx.x;
    int combo = blockIdx.y;               // 24 = 8 rows x 3 pairs
    int row = combo / 3, i = combo % 3;
    const uint4* __restrict__ A = (const uint4*)g_A[row][i];
    const uint4* __restrict__ C = (const uint4*)g_C[row][i];
    const int n = T_LEN / 8;
    float acc = 0.0f;
    for (int v = blockIdx.x * 256 + tid; v < n; v += P3BLKS * 256) {
        uint4 a = A[v], c = C[v];
        const __half2* ha = (const __half2*)&a;
        const __half2* hc = (const __half2*)&c;
#pragma unroll
        for (int q = 0; q < 4; q++) {
            __half2 d = __habs2(__hsub2(ha[q], hc[q]));
            float2 f = __half22float2(d);
            acc += f.x + f.y;
        }
    }
    __shared__ float sh[256];
    sh[tid] = acc;
    __syncthreads();
    for (int s = 128; s > 0; s >>= 1) {
        if (tid < s) sh[tid] += sh[tid + s];
        __syncthreads();
    }
    if (tid == 0) g_part[combo * P3BLKS + blockIdx.x] = sh[0];
}

__global__ void final_kernel(float* __restrict__ out) {
    __shared__ float sh[1024];
    int tid = threadIdx.x;
    float v = 0.0f;
    for (int i = tid; i < 24 * P3BLKS; i += 1024) v += g_part[i];
    sh[tid] = v;
    __syncthreads();
    for (int s = 512; s > 0; s >>= 1) {
        if (tid < s) sh[tid] += sh[tid + s];
        __syncthreads();
    }
    if (tid == 0)
        out[0] = (float)((double)sh[0] * 0.69314718055994530942 / (8.0 * (double)T_LEN));
}

extern "C" void kernel_launch(void* const* d_in, const int* in_sizes, int n_in,
                              void* d_out, int out_size) {
    const float* xp = (const float*)d_in[0];
    const float* xt = (const float*)d_in[1];
    (void)in_sizes; (void)n_in; (void)out_size;

    Consts K;
    const double sr = 44100.0;
    const double s_taus[3] = {10.0, 50.0, 100.0};
    const double l_taus[3] = {500.0, 1500.0, 3000.0};
    int shifts[3];
    for (int i = 0; i < 3; i++) {
        K.c[i]     = (float)(1.0 - exp(-2200.0 / (s_taus[i] * sr)));
        K.c[3 + i] = (float)(1.0 - exp(-2200.0 / (l_taus[i] * sr)));
        shifts[i]  = (int)(sr * (l_taus[i] - s_taus[i]) * 0.0005);
    }
    for (int k = 0; k < 6; k++) {
        K.a[k]  = 1.0f - K.c[k];
        K.aC[k] = (float)pow((double)K.a[k], (double)CPT);
        K.aL[k] = (float)pow((double)K.a[k], (double)CHUNK);
    }

    dim3 grid(NCHUNK, NB);
    pass1_kernel<<<grid, BLK>>>(xp, xt, K);
    mid_kernel<<<96, 32>>>(K);
    pass2_kernel<<<grid, BLK>>>(xp, xt, K, shifts[0], shifts[1], shifts[2]);
    dim3 g3(P3BLKS, 24);
    pass3_kernel<<<g3, 256>>>();
    final_kernel<<<1, 1024>>>((float*)d_out);
}

// round 4
// speedup vs baseline: 2.1175x; 1.2121x over previous
#include <cuda_runtime.h>
#include <cuda_fp16.h>
#include <math.h>

#define T_LEN  (1 << 20)
#define CPT    16                  // elements per thread
#define BLK    256
#define CHUNK  (BLK * CPT)         // 4096
#define NCHUNK (T_LEN / CHUNK)     // 256
#define NB     4
#define EPSF   1e-8f
#define P3BLKS 64

struct Consts {
    float a[6];   // 1 - c
    float aC[6];  // a^CPT
    float aL[6];  // a^CHUNK
};

// Static device scratch (no cudaMalloc allowed)
__device__ __align__(128) float g_tot[NB][NCHUNK][32];   // chunk-local totals, padded to 128B
__device__ int   g_flag[NB][NCHUNK];
__device__ __align__(16) __half g_A[8][3][T_LEN];        // short log-diff, swizzled addr(t)
__device__ __align__(16) __half g_C[8][3][T_LEN];        // long  log-diff, stored pre-shifted
__device__ float g_part[24 * P3BLKS];

__device__ __forceinline__ int ld_acquire(const int* p) {
    int v;
    asm volatile("ld.acquire.gpu.b32 %0, [%1];" : "=r"(v) : "l"(p) : "memory");
    return v;
}
__device__ __forceinline__ void st_release(int* p, int v) {
    asm volatile("st.release.gpu.b32 [%0], %1;" :: "l"(p), "r"(v) : "memory");
}

// out[k] = base[k]^e via exact squaring ladder (e <= 255)
__device__ __forceinline__ void pow_ladder(float* out, const float* base, int e) {
#pragma unroll
    for (int k = 0; k < 6; k++) {
        float p = 1.0f, b = base[k];
        int ee = e;
#pragma unroll
        for (int bit = 0; bit < 8; bit++) { if (ee & 1) p *= b; b *= b; ee >>= 1; }
        out[k] = p;
    }
}

// z-chains (c factored out; cancels in log-differences):
// ch = rm*12 + sig*6 + k (rm 0=mid 1=side; sig 0=pred 1=true; k 0..2 short, 3..5 long)
__device__ __forceinline__ void chain_update(float* z, const Consts& K,
                                             float vpm, float vtm, float vps, float vts) {
#pragma unroll
    for (int k = 0; k < 6; k++) {
        z[k]      = fmaf(K.a[k], z[k],      vpm);
        z[6 + k]  = fmaf(K.a[k], z[6 + k],  vtm);
        z[12 + k] = fmaf(K.a[k], z[12 + k], vps);
        z[18 + k] = fmaf(K.a[k], z[18 + k], vts);
    }
}

#define DO_ELEM(e) {                                                         \
    float sm = a0.e + a1.e, sd = a0.e - a1.e;                                \
    float tm = b0.e + b1.e, td = b0.e - b1.e;                                \
    chain_update(y, K, fmaxf(0.5f * sm * sm, EPSF),                          \
                       fmaxf(0.5f * tm * tm, EPSF),                          \
                       fmaxf(0.5f * sd * sd, EPSF),                          \
                       fmaxf(0.5f * td * td, EPSF)); }

__device__ __forceinline__ void local_accum(float* y, const Consts& K,
        const float4* __restrict__ p0, const float4* __restrict__ p1,
        const float4* __restrict__ q0, const float4* __restrict__ q1) {
#pragma unroll
    for (int jj = 0; jj < CPT / 4; jj++) {
        float4 a0 = p0[jj], a1 = p1[jj], b0 = q0[jj], b1 = q1[jj];
        DO_ELEM(x) DO_ELEM(y) DO_ELEM(z) DO_ELEM(w)
    }
}

__global__ void clear_kernel() {
    int i = threadIdx.x;
    if (i < NB * NCHUNK) ((int*)g_flag)[i] = 0;
}

__global__ __launch_bounds__(BLK) void fused_kernel(const float* __restrict__ xp,
                                                    const float* __restrict__ xt, Consts K,
                                                    int sh0, int sh1, int sh2) {
    __shared__ float wagg[24][8];   // exclusive warp prefixes
    __shared__ float cagg[24][8];   // lookback cross-warp partials
    __shared__ float tot_s[24];     // block totals
    __shared__ float cb_s[24];      // chunk carry-in

    int g = blockIdx.x, b = blockIdx.y, tid = threadIdx.x;
    int lane = tid & 31, warp = tid >> 5;
    size_t base = (size_t)g * CHUNK + (size_t)tid * CPT;
    const float4* p0 = (const float4*)(xp + (size_t)(b * 2 + 0) * T_LEN + base);
    const float4* p1 = (const float4*)(xp + (size_t)(b * 2 + 1) * T_LEN + base);
    const float4* q0 = (const float4*)(xt + (size_t)(b * 2 + 0) * T_LEN + base);
    const float4* q1 = (const float4*)(xt + (size_t)(b * 2 + 1) * T_LEN + base);

    // ── Phase A: per-thread local totals + warp decayed scan ──
    float y[24];
#pragma unroll
    for (int c = 0; c < 24; c++) y[c] = 0.0f;
    local_accum(y, K, p0, p1, q0, q1);

    float pw[6];
#pragma unroll
    for (int k = 0; k < 6; k++) pw[k] = K.aC[k];
#pragma unroll
    for (int off = 1; off < 32; off <<= 1) {
#pragma unroll
        for (int c = 0; c < 24; c++) {
            float up = __shfl_up_sync(0xffffffffu, y[c], off);
            if (lane >= off) y[c] = fmaf(pw[c % 6], up, y[c]);
        }
#pragma unroll
        for (int k = 0; k < 6; k++) pw[k] *= pw[k];   // ends at aC^32
    }
    if (lane == 31) {
#pragma unroll
        for (int c = 0; c < 24; c++) wagg[c][warp] = y[c];
    }
    __syncthreads();
    if (tid < 24) {
        float p = 0.0f, aW = pw[tid % 6];
#pragma unroll
        for (int w = 0; w < 8; w++) {
            float t = wagg[tid][w];
            wagg[tid][w] = p;               // exclusive warp prefix
            p = fmaf(aW, p, t);
        }
        tot_s[tid] = p;                     // block total
    }
    __syncthreads();

    // ── Publish local totals ASAP (before any waiting!) ──
    if (tid == 0) {
        float4* dst = (float4*)g_tot[b][g];
#pragma unroll
        for (int q = 0; q < 6; q++) dst[q] = ((float4*)tot_s)[q];
        st_release(&g_flag[b][g], 1);
    }

    // ── Thread-exclusive local prefix (block scope, no global carry yet) ──
    float cin[24];
    {
        float alane[6];
        pow_ladder(alane, K.aC, lane + 1);
#pragma unroll
        for (int c = 0; c < 24; c++) {
            float P  = wagg[c][warp];
            float bi = fmaf(alane[c % 6], P, y[c]);        // block-inclusive
            float pr = __shfl_up_sync(0xffffffffu, bi, 1);
            cin[c] = (lane == 0) ? P : pr;
        }
    }

    // ── Phase B: decoupled lookback — carry = sum_d aL^d * local(g-1-d) ──
    float contrib[24];
#pragma unroll
    for (int c = 0; c < 24; c++) contrib[c] = 0.0f;
    if (tid < g) {
        int j = g - 1 - tid;
        float wd[6];
        pow_ladder(wd, K.aL, tid);
        while (!ld_acquire(&g_flag[b][j])) __nanosleep(64);
        const float4* tp = (const float4*)g_tot[b][j];
#pragma unroll
        for (int q = 0; q < 6; q++) {
            float4 v4 = __ldcg(tp + q);
            contrib[q * 4 + 0] = wd[(q * 4 + 0) % 6] * v4.x;
            contrib[q * 4 + 1] = wd[(q * 4 + 1) % 6] * v4.y;
            contrib[q * 4 + 2] = wd[(q * 4 + 2) % 6] * v4.z;
            contrib[q * 4 + 3] = wd[(q * 4 + 3) % 6] * v4.w;
        }
    }
#pragma unroll
    for (int off = 16; off > 0; off >>= 1) {
#pragma unroll
        for (int c = 0; c < 24; c++)
            contrib[c] += __shfl_xor_sync(0xffffffffu, contrib[c], off);
    }
    if (lane == 0) {
#pragma unroll
        for (int c = 0; c < 24; c++) cagg[c][warp] = contrib[c];
    }
    __syncthreads();
    if (tid < 24) {
        float s = 0.0f;
#pragma unroll
        for (int w = 0; w < 8; w++) s += cagg[tid][w];
        cb_s[tid] = s;
    }
    __syncthreads();

    {   // fold chunk carry into per-thread carry-in: cin += aC^tid * carry
        float atid[6];
        pow_ladder(atid, K.aC, tid);
#pragma unroll
        for (int c = 0; c < 24; c++) cin[c] = fmaf(atid[c % 6], cb_s[c], cin[c]);
    }

    // ── Phase C: replay chains with exact state, emit fp16 log-diffs ──
    int row0 = b * 2, row1 = b * 2 + 1;
    int obase = g * CHUNK;
    int shifts[3] = {sh0, sh1, sh2};

#pragma unroll
    for (int jj = 0; jj < CPT / 4; jj++) {
        float4 a0 = p0[jj], a1 = p1[jj], b0 = q0[jj], b1 = q1[jj];
#define OUT_ELEM(e, eidx) {                                                      \
        float sm = a0.e + a1.e, sd = a0.e - a1.e;                                \
        float tm = b0.e + b1.e, td = b0.e - b1.e;                                \
        chain_update(cin, K, fmaxf(0.5f * sm * sm, EPSF),                        \
                             fmaxf(0.5f * tm * tm, EPSF),                        \
                             fmaxf(0.5f * sd * sd, EPSF),                        \
                             fmaxf(0.5f * td * td, EPSF));                       \
        int el = jj * 4 + eidx;                                                  \
        int addr = obase + el * BLK + tid;                                       \
        int t = obase + tid * CPT + el;                                          \
        _Pragma("unroll")                                                        \
        for (int i = 0; i < 3; i++) {                                            \
            g_A[row0][i][addr] = __float2half(__log2f(cin[i])      - __log2f(cin[6 + i]));  \
            g_A[row1][i][addr] = __float2half(__log2f(cin[12 + i]) - __log2f(cin[18 + i])); \
            int t2 = (t - shifts[i]) & (T_LEN - 1);                              \
            int caddr = (t2 & ~(CHUNK - 1)) | ((t2 & (CPT - 1)) << 8)            \
                      | ((t2 & (CHUNK - 1)) >> 4);                               \
            g_C[row0][i][caddr] = __float2half(__log2f(cin[3 + i])  - __log2f(cin[9 + i]));  \
            g_C[row1][i][caddr] = __float2half(__log2f(cin[15 + i]) - __log2f(cin[21 + i])); \
        } }
        OUT_ELEM(x, 0) OUT_ELEM(y, 1) OUT_ELEM(z, 2) OUT_ELEM(w, 3)
#undef OUT_ELEM
    }
}

// Both streams linear + 16B aligned (long side pre-shifted at write time).
__global__ __launch_bounds__(256) void pass3_kernel() {
    int tid = threadIdx.x;
    int combo = blockIdx.y;               // 24 = 8 rows x 3 pairs
    int row = combo / 3, i = combo % 3;
    const uint4* __restrict__ A = (const uint4*)g_A[row][i];
    const uint4* __restrict__ C = (const uint4*)g_C[row][i];
    const int n = T_LEN / 8;
    float acc = 0.0f;
    for (int v = blockIdx.x * 256 + tid; v < n; v += P3BLKS * 256) {
        uint4 a = A[v], c = C[v];
        const __half2* ha = (const __half2*)&a;
        const __half2* hc = (const __half2*)&c;
#pragma unroll
        for (int q = 0; q < 4; q++) {
            __half2 d = __habs2(__hsub2(ha[q], hc[q]));
            float2 f = __half22float2(d);
            acc += f.x + f.y;
        }
    }
    __shared__ float sh[256];
    sh[tid] = acc;
    __syncthreads();
    for (int s = 128; s > 0; s >>= 1) {
        if (tid < s) sh[tid] += sh[tid + s];
        __syncthreads();
    }
    if (tid == 0) g_part[combo * P3BLKS + blockIdx.x] = sh[0];
}

__global__ void final_kernel(float* __restrict__ out) {
    __shared__ float sh[1024];
    int tid = threadIdx.x;
    float v = 0.0f;
    for (int i = tid; i < 24 * P3BLKS; i += 1024) v += g_part[i];
    sh[tid] = v;
    __syncthreads();
    for (int s = 512; s > 0; s >>= 1) {
        if (tid < s) sh[tid] += sh[tid + s];
        __syncthreads();
    }
    if (tid == 0)
        out[0] = (float)((double)sh[0] * 0.69314718055994530942 / (8.0 * (double)T_LEN));
}

extern "C" void kernel_launch(void* const* d_in, const int* in_sizes, int n_in,
                              void* d_out, int out_size) {
    const float* xp = (const float*)d_in[0];
    const float* xt = (const float*)d_in[1];
    (void)in_sizes; (void)n_in; (void)out_size;

    Consts K;
    const double sr = 44100.0;
    const double s_taus[3] = {10.0, 50.0, 100.0};
    const double l_taus[3] = {500.0, 1500.0, 3000.0};
    int shifts[3];
    float cco[6];
    for (int i = 0; i < 3; i++) {
        cco[i]     = (float)(1.0 - exp(-2200.0 / (s_taus[i] * sr)));
        cco[3 + i] = (float)(1.0 - exp(-2200.0 / (l_taus[i] * sr)));
        shifts[i]  = (int)(sr * (l_taus[i] - s_taus[i]) * 0.0005);
    }
    for (int k = 0; k < 6; k++) {
        K.a[k]  = 1.0f - cco[k];
        K.aC[k] = (float)pow((double)K.a[k], (double)CPT);
        K.aL[k] = (float)pow((double)K.a[k], (double)CHUNK);
    }

    clear_kernel<<<1, 1024>>>();
    dim3 grid(NCHUNK, NB);
    fused_kernel<<<grid, BLK>>>(xp, xt, K, shifts[0], shifts[1], shifts[2]);
    dim3 g3(P3BLKS, 24);
    pass3_kernel<<<g3, 256>>>();
    final_kernel<<<1, 1024>>>((float*)d_out);
}